// round 10
// baseline (speedup 1.0000x reference)
#include <cuda_runtime.h>
#include <cuda_bf16.h>
#include <cstdint>
#include <cstddef>

#define B_   4
#define S_   4096
#define D_   2048
#define E_   64
#define N_   (B_*S_)          // 16384
#define TM   32               // tokens per block
#define NBLK (N_/TM)          // 512 blocks
#define KC   32               // k per chunk
#define NCH  (D_/KC)          // 64 chunks
#define NBPB (S_/TM)          // 128 blocks per batch

// smem tiles: bf16, row stride 40 elems = 80B (conflict-free ldmatrix)
#define OFF_AHI 0
#define OFF_ALO (TM*80)           // 2560
#define OFF_BHI (2*TM*80)         // 5120
#define OFF_BLO (2*TM*80 + E_*80) // 10240
#define EPI_BYTES (2*TM*68*4)     // 17408 B (union over 15360 B of tiles)

__device__ float g_load_part[NBLK][E_];
__device__ float g_z_part[NBLK];
__device__ unsigned int g_cnt = 0;

__device__ __forceinline__ uint32_t smem_u32(const void* p) {
    uint32_t a;
    asm("{ .reg .u64 t; cvta.to.shared.u64 t, %1; cvt.u32.u64 %0, t; }" : "=r"(a) : "l"(p));
    return a;
}
__device__ __forceinline__ void ldsm4(uint32_t* r, uint32_t addr) {
    asm volatile("ldmatrix.sync.aligned.m8n8.x4.shared.b16 {%0,%1,%2,%3}, [%4];"
                 : "=r"(r[0]), "=r"(r[1]), "=r"(r[2]), "=r"(r[3]) : "r"(addr));
}
__device__ __forceinline__ void mma_bf16(float* d, const uint32_t* a, uint32_t b0, uint32_t b1) {
    asm volatile(
        "mma.sync.aligned.m16n8k16.row.col.f32.bf16.bf16.f32 "
        "{%0,%1,%2,%3}, {%4,%5,%6,%7}, {%8,%9}, {%0,%1,%2,%3};"
        : "+f"(d[0]), "+f"(d[1]), "+f"(d[2]), "+f"(d[3])
        : "r"(a[0]), "r"(a[1]), "r"(a[2]), "r"(a[3]), "r"(b0), "r"(b1));
}
__device__ __forceinline__ void cvt_hilo(float a, float b, uint32_t &hi, uint32_t &lo) {
    __nv_bfloat162 h = __floats2bfloat162_rn(a, b);
    hi = *reinterpret_cast<uint32_t*>(&h);
    float ra = a - __bfloat162float(h.x);
    float rb = b - __bfloat162float(h.y);
    __nv_bfloat162 l = __floats2bfloat162_rn(ra, rb);
    lo = *reinterpret_cast<uint32_t*>(&l);
}

__global__ void __launch_bounds__(256) router_main(
    const float* __restrict__ x, const float* __restrict__ W,
    const float* __restrict__ gamma, const float* __restrict__ beta,
    const float* __restrict__ temp,
    float* __restrict__ out_rw, float* __restrict__ out_disp,
    float* __restrict__ out_loss)
{
    __shared__ __align__(16) char smtiles[EPI_BYTES];   // tiles, then epi[2][32][68]
    __shared__ float s_exl[8][E_];
    __shared__ float s_z[8];
    __shared__ unsigned int s_last;

    const uint32_t sb = smem_u32(smtiles);
    const int tid = threadIdx.x;
    const int wid = tid >> 5, lane = tid & 31;
    const int blk = blockIdx.x;
    const int gt0 = blk * TM;

    // ---- fill mapping ----
    const int arow = tid >> 3, ak0 = (tid & 7) * 4;     // A: 8 thr/row, 1 float4
    const int brow = tid >> 2, bk0 = (tid & 3) * 8;     // B: 4 thr/row, 2 float4
    const float* xbase = x + (size_t)(gt0 + arow) * D_ + ak0;
    const float* wbase = W + (size_t)brow * D_ + bk0;

    float4 px, pw[2];
    px = *(const float4*)(xbase);
    #pragma unroll
    for (int i = 0; i < 2; i++) pw[i] = *(const float4*)(wbase + 4*i);

    // ---- warp tile: m32 x n16 x k16 (ng: 4 n-groups, kg: 2 k-halves) ----
    const int ng = wid & 3, kg = wid >> 2;
    const int g = lane >> 3, rif = lane & 7;
    const uint32_t kgb = (uint32_t)kg * 32u;    // k16 byte offset
    uint32_t aoff[2];
    #pragma unroll
    for (int s = 0; s < 2; s++)
        aoff[s] = (uint32_t)(s*16 + (g & 1)*8 + rif) * 80u + (uint32_t)((g >> 1)*8) * 2u + kgb;
    const uint32_t boff = (uint32_t)(ng*16 + (g >> 1)*8 + rif) * 80u + (uint32_t)((g & 1)*8) * 2u + kgb;

    float acc[2][2][4];
    #pragma unroll
    for (int s = 0; s < 2; s++)
        #pragma unroll
        for (int j = 0; j < 2; j++)
            #pragma unroll
            for (int i = 0; i < 4; i++) acc[s][j][i] = 0.0f;

    for (int c = 0; c < NCH; c++) {
        // stage regs -> smem (bf16 hi/lo)
        {
            const uint32_t abyt = (uint32_t)arow * 80u + (uint32_t)ak0 * 2u;
            uint32_t h01, l01, h23, l23;
            cvt_hilo(px.x, px.y, h01, l01);
            cvt_hilo(px.z, px.w, h23, l23);
            *(uint2*)(smtiles + OFF_AHI + abyt) = make_uint2(h01, h23);
            *(uint2*)(smtiles + OFF_ALO + abyt) = make_uint2(l01, l23);
            #pragma unroll
            for (int i = 0; i < 2; i++) {
                const uint32_t bbyt = (uint32_t)brow * 80u + (uint32_t)(bk0 + 4*i) * 2u;
                uint32_t wh01, wl01, wh23, wl23;
                cvt_hilo(pw[i].x, pw[i].y, wh01, wl01);
                cvt_hilo(pw[i].z, pw[i].w, wh23, wl23);
                *(uint2*)(smtiles + OFF_BHI + bbyt) = make_uint2(wh01, wh23);
                *(uint2*)(smtiles + OFF_BLO + bbyt) = make_uint2(wl01, wl23);
            }
        }
        __syncthreads();

        if (c + 1 < NCH) {
            const int kb = (c + 1) * KC;
            px = *(const float4*)(xbase + kb);
            #pragma unroll
            for (int i = 0; i < 2; i++) pw[i] = *(const float4*)(wbase + kb + 4*i);
        }

        // one k16 step per warp (its k-half): 6 LDSM.x4 + 12 MMA
        uint32_t ah[2][4], al[2][4], bh[4], bl[4];
        ldsm4(ah[0], sb + OFF_AHI + aoff[0]);
        ldsm4(ah[1], sb + OFF_AHI + aoff[1]);
        ldsm4(al[0], sb + OFF_ALO + aoff[0]);
        ldsm4(al[1], sb + OFF_ALO + aoff[1]);
        ldsm4(bh, sb + OFF_BHI + boff);
        #pragma unroll
        for (int s = 0; s < 2; s++)
            #pragma unroll
            for (int j = 0; j < 2; j++) {
                mma_bf16(acc[s][j], ah[s], bh[2*j], bh[2*j + 1]);   // hi*hi
                mma_bf16(acc[s][j], al[s], bh[2*j], bh[2*j + 1]);   // lo*hi
            }
        ldsm4(bl, sb + OFF_BLO + boff);
        #pragma unroll
        for (int s = 0; s < 2; s++)
            #pragma unroll
            for (int j = 0; j < 2; j++)
                mma_bf16(acc[s][j], ah[s], bl[2*j], bl[2*j + 1]);   // hi*lo
        __syncthreads();
    }

    // ---- acc -> epi[kg][32][68] (k-half partials) ----
    float* epi = (float*)smtiles;
    {
        float* ep = epi + kg * TM * 68;
        const int rl = lane >> 2;
        const int cq = (lane & 3) * 2;
        #pragma unroll
        for (int s = 0; s < 2; s++) {
            const int r0 = s*16 + rl;
            #pragma unroll
            for (int j = 0; j < 2; j++) {
                const int col = ng*16 + j*8 + cq;
                *(float2*)&ep[(r0    )*68 + col] = make_float2(acc[s][j][0], acc[s][j][1]);
                *(float2*)&ep[(r0 + 8)*68 + col] = make_float2(acc[s][j][2], acc[s][j][3]);
            }
        }
    }
    __syncthreads();

    // ---- LN / softmax / top-2 (8 warps x 4 tokens) ----
    const float g0v = gamma[lane], g1v = gamma[lane + 32];
    const float bb0 = beta[lane], bb1 = beta[lane + 32];
    const float invt = 1.0f / (temp[0] + 1e-6f);

    for (int e = lane; e < E_; e += 32) s_exl[wid][e] = 0.0f;

    float zacc = 0.0f;
    for (int t = wid*4; t < wid*4 + 4; t++) {
        const float v0 = epi[t*68 + lane]      + epi[TM*68 + t*68 + lane];
        const float v1 = epi[t*68 + lane + 32] + epi[TM*68 + t*68 + lane + 32];
        float sm = v0 + v1;
        #pragma unroll
        for (int o = 16; o; o >>= 1) sm += __shfl_xor_sync(~0u, sm, o);
        const float mu = sm * (1.0f/64.0f);
        const float d0 = v0 - mu, d1 = v1 - mu;
        float q = d0*d0 + d1*d1;
        #pragma unroll
        for (int o = 16; o; o >>= 1) q += __shfl_xor_sync(~0u, q, o);
        const float inv = rsqrtf(q * (1.0f/64.0f) + 1e-5f);
        const float y0 = d0*inv*g0v + bb0;
        const float y1 = d1*inv*g1v + bb1;
        zacc += y0*y0 + y1*y1;
        const float sc0 = y0*invt, sc1 = y1*invt;
        float m = fmaxf(sc0, sc1);
        #pragma unroll
        for (int o = 16; o; o >>= 1) m = fmaxf(m, __shfl_xor_sync(~0u, m, o));
        const float ex0 = __expf(sc0 - m), ex1 = __expf(sc1 - m);
        float es = ex0 + ex1;
        #pragma unroll
        for (int o = 16; o; o >>= 1) es += __shfl_xor_sync(~0u, es, o);
        const float rinv = 1.0f / es;
        const float p0 = ex0 * rinv, p1 = ex1 * rinv;
        float bv; int bi;
        if (p0 >= p1) { bv = p0; bi = lane; } else { bv = p1; bi = lane + 32; }
        #pragma unroll
        for (int o = 16; o; o >>= 1) {
            float ov = __shfl_xor_sync(~0u, bv, o);
            int   oi = __shfl_xor_sync(~0u, bi, o);
            if (ov > bv || (ov == bv && oi < bi)) { bv = ov; bi = oi; }
        }
        const float w1 = bv; const int i1 = bi;
        const float c0 = (lane      == i1) ? -1.0f : p0;
        const float c1 = (lane + 32 == i1) ? -1.0f : p1;
        if (c0 >= c1) { bv = c0; bi = lane; } else { bv = c1; bi = lane + 32; }
        #pragma unroll
        for (int o = 16; o; o >>= 1) {
            float ov = __shfl_xor_sync(~0u, bv, o);
            int   oi = __shfl_xor_sync(~0u, bi, o);
            if (ov > bv || (ov == bv && oi < bi)) { bv = ov; bi = oi; }
        }
        const float w2 = bv; const int i2 = bi;

        const size_t base = (size_t)(gt0 + t) * E_;
        out_rw[base + lane]      = p0;
        out_rw[base + lane + 32] = p1;
        out_disp[base + lane]      = (lane == i1 || lane == i2)           ? p0 : 0.0f;
        out_disp[base + lane + 32] = (lane + 32 == i1 || lane + 32 == i2) ? p1 : 0.0f;

        if (i1 == lane)           s_exl[wid][lane]      += w1;
        else if (i1 == lane + 32) s_exl[wid][lane + 32] += w1;
        if (i2 == lane)           s_exl[wid][lane]      += w2;
        else if (i2 == lane + 32) s_exl[wid][lane + 32] += w2;
    }
    #pragma unroll
    for (int o = 16; o; o >>= 1) zacc += __shfl_xor_sync(~0u, zacc, o);
    if (lane == 0) s_z[wid] = zacc;
    __syncthreads();

    if (tid < E_) {
        float a = 0.0f;
        #pragma unroll
        for (int w = 0; w < 8; w++) a += s_exl[w][tid];
        g_load_part[blk][tid] = a;
    }
    if (tid == 0)
        g_z_part[blk] = s_z[0]+s_z[1]+s_z[2]+s_z[3]+s_z[4]+s_z[5]+s_z[6]+s_z[7];

    // ---- last-block finalize (deterministic) ----
    __threadfence();
    if (tid == 0) s_last = (atomicAdd(&g_cnt, 1) == NBLK - 1) ? 1u : 0u;
    __syncthreads();
    if (!s_last) return;
    if (tid == 0) g_cnt = 0;
    __threadfence();

    float* red = (float*)smtiles;
    const int b = tid >> 6, e = tid & 63;
    float l = 0.0f;
    #pragma unroll 8
    for (int k = 0; k < NBPB; k++) l += g_load_part[b * NBPB + k][e];
    l *= (1.0f / S_);
    float zc = 0.0f;
    #pragma unroll 2
    for (int h = 0; h < NBLK/256; h++) zc += g_z_part[tid + h*256];

    __syncthreads();
    red[tid] = l; __syncthreads();
    for (int o = 128; o; o >>= 1) { if (tid < o) red[tid] += red[tid + o]; __syncthreads(); }
    const float mean = red[0] * (1.0f / 256.0f);
    __syncthreads();

    const float dd = l - mean;
    red[tid] = dd * dd; __syncthreads();
    for (int o = 128; o; o >>= 1) { if (tid < o) red[tid] += red[tid + o]; __syncthreads(); }
    const float var = red[0] * (1.0f / 255.0f);
    __syncthreads();

    red[tid] = zc; __syncthreads();
    for (int o = 128; o; o >>= 1) { if (tid < o) red[tid] += red[tid + o]; __syncthreads(); }

    if (tid == 0) {
        const float zmean = red[0] / (float)((size_t)N_ * E_);
        const float lb = (sqrtf(var) / mean) * 10.0f;
        out_loss[0] = 0.001f * zmean + 0.1f * lb;
    }
}

extern "C" void kernel_launch(void* const* d_in, const int* in_sizes, int n_in,
                              void* d_out, int out_size)
{
    (void)in_sizes; (void)n_in; (void)out_size;
    const float* x     = (const float*)d_in[0];
    const float* W     = (const float*)d_in[1];
    const float* gamma = (const float*)d_in[2];
    const float* beta  = (const float*)d_in[3];
    const float* temp  = (const float*)d_in[4];

    float* out  = (float*)d_out;
    float* rw   = out;
    float* disp = out + (size_t)N_ * E_;
    float* loss = out + (size_t)2 * N_ * E_;

    router_main<<<NBLK, 256>>>(x, W, gamma, beta, temp, rw, disp, loss);
}

// round 11
// speedup vs baseline: 1.5247x; 1.5247x over previous
#include <cuda_runtime.h>
#include <cuda_bf16.h>
#include <cstdint>
#include <cstddef>

#define B_   4
#define S_   4096
#define D_   2048
#define E_   64
#define N_   (B_*S_)          // 16384
#define TM   64               // tokens per block
#define NBLK (N_/TM)          // 256 blocks
#define KC   32               // k per chunk
#define NCH  (D_/KC)          // 64 chunks
#define NBPB (S_/TM)          // 64 blocks per batch

// smem tiles: bf16, row stride 40 elems = 80B (conflict-free ldmatrix)
// two stages of 20480B each; epi[2][64][68] (34816B) aliases the region
#define SSZ  20480
#define OFF_AHI 0
#define OFF_ALO (TM*80)           // 5120
#define OFF_BHI (2*TM*80)         // 10240
#define OFF_BLO (2*TM*80 + E_*80) // 15360
#define SM_BYTES (2*SSZ)          // 40960

__device__ float g_load_part[NBLK][E_];
__device__ float g_z_part[NBLK];
__device__ unsigned int g_cnt = 0;

__device__ __forceinline__ uint32_t smem_u32(const void* p) {
    uint32_t a;
    asm("{ .reg .u64 t; cvta.to.shared.u64 t, %1; cvt.u32.u64 %0, t; }" : "=r"(a) : "l"(p));
    return a;
}
__device__ __forceinline__ void ldsm4(uint32_t* r, uint32_t addr) {
    asm volatile("ldmatrix.sync.aligned.m8n8.x4.shared.b16 {%0,%1,%2,%3}, [%4];"
                 : "=r"(r[0]), "=r"(r[1]), "=r"(r[2]), "=r"(r[3]) : "r"(addr));
}
__device__ __forceinline__ void mma_bf16(float* d, const uint32_t* a, uint32_t b0, uint32_t b1) {
    asm volatile(
        "mma.sync.aligned.m16n8k16.row.col.f32.bf16.bf16.f32 "
        "{%0,%1,%2,%3}, {%4,%5,%6,%7}, {%8,%9}, {%0,%1,%2,%3};"
        : "+f"(d[0]), "+f"(d[1]), "+f"(d[2]), "+f"(d[3])
        : "r"(a[0]), "r"(a[1]), "r"(a[2]), "r"(a[3]), "r"(b0), "r"(b1));
}
__device__ __forceinline__ void cvt_hilo(float a, float b, uint32_t &hi, uint32_t &lo) {
    __nv_bfloat162 h = __floats2bfloat162_rn(a, b);
    hi = *reinterpret_cast<uint32_t*>(&h);
    float ra = a - __bfloat162float(h.x);
    float rb = b - __bfloat162float(h.y);
    __nv_bfloat162 l = __floats2bfloat162_rn(ra, rb);
    lo = *reinterpret_cast<uint32_t*>(&l);
}

__global__ void __launch_bounds__(256) router_main(
    const float* __restrict__ x, const float* __restrict__ W,
    const float* __restrict__ gamma, const float* __restrict__ beta,
    const float* __restrict__ temp,
    float* __restrict__ out_rw, float* __restrict__ out_disp,
    float* __restrict__ out_loss)
{
    __shared__ __align__(16) char smtiles[SM_BYTES];   // 2-stage tiles; epi aliases
    __shared__ float s_exl[8][E_];
    __shared__ float s_z[8];
    __shared__ unsigned int s_last;

    const uint32_t sb = smem_u32(smtiles);
    const int tid = threadIdx.x;
    const int wid = tid >> 5, lane = tid & 31;
    const int blk = blockIdx.x;
    const int gt0 = blk * TM;

    // ---- fill mapping: 4 thr/row, 8 floats each (both tiles are 64 x 32) ----
    const int frow = tid >> 2, fk0 = (tid & 3) * 8;
    const float* xbase = x + (size_t)(gt0 + frow) * D_ + fk0;
    const float* wbase = W + (size_t)frow * D_ + fk0;

    float4 px[2], pw[2];
    #pragma unroll
    for (int i = 0; i < 2; i++) px[i] = *(const float4*)(xbase + 4*i);
    #pragma unroll
    for (int i = 0; i < 2; i++) pw[i] = *(const float4*)(wbase + 4*i);

    // ---- warp tile: m32 x n32 x k-half ----
    const int mg = wid & 1, ng = (wid >> 1) & 1, kg = wid >> 2;
    const int g = lane >> 3, rif = lane & 7;
    const uint32_t kgb = (uint32_t)kg * 32u;    // k16 offset in bytes
    uint32_t aoff[2], boff[2];
    #pragma unroll
    for (int s = 0; s < 2; s++)
        aoff[s] = (uint32_t)(mg*32 + s*16 + (g & 1)*8 + rif) * 80u + (uint32_t)((g >> 1)*8) * 2u + kgb;
    #pragma unroll
    for (int j = 0; j < 2; j++)
        boff[j] = (uint32_t)(ng*32 + j*16 + (g >> 1)*8 + rif) * 80u + (uint32_t)((g & 1)*8) * 2u + kgb;

    float acc[2][4][4];
    #pragma unroll
    for (int s = 0; s < 2; s++)
        #pragma unroll
        for (int j = 0; j < 4; j++)
            #pragma unroll
            for (int i = 0; i < 4; i++) acc[s][j][i] = 0.0f;

    const uint32_t fbytA = (uint32_t)frow * 80u + (uint32_t)fk0 * 2u;

    // ---- prologue: stage chunk 0 into buffer 0 ----
    #pragma unroll
    for (int i = 0; i < 2; i++) {
        const uint32_t byt = fbytA + (uint32_t)(4*i) * 2u;
        uint32_t h01, l01, h23, l23;
        cvt_hilo(px[i].x, px[i].y, h01, l01);
        cvt_hilo(px[i].z, px[i].w, h23, l23);
        *(uint2*)(smtiles + OFF_AHI + byt) = make_uint2(h01, h23);
        *(uint2*)(smtiles + OFF_ALO + byt) = make_uint2(l01, l23);
        uint32_t wh01, wl01, wh23, wl23;
        cvt_hilo(pw[i].x, pw[i].y, wh01, wl01);
        cvt_hilo(pw[i].z, pw[i].w, wh23, wl23);
        *(uint2*)(smtiles + OFF_BHI + byt) = make_uint2(wh01, wh23);
        *(uint2*)(smtiles + OFF_BLO + byt) = make_uint2(wl01, wl23);
    }
    __syncthreads();

    #pragma unroll 2
    for (int c = 0; c < NCH; c++) {
        const uint32_t cst = (uint32_t)(c & 1) * SSZ;      // compute stage base
        const uint32_t nst = cst ^ SSZ;                    // next stage base

        // LDG chunk c+1 (lands during MMA below)
        if (c + 1 < NCH) {
            const int kb = (c + 1) * KC;
            #pragma unroll
            for (int i = 0; i < 2; i++) px[i] = *(const float4*)(xbase + kb + 4*i);
            #pragma unroll
            for (int i = 0; i < 2; i++) pw[i] = *(const float4*)(wbase + kb + 4*i);
        }

        // one k16 step per warp (its k-half) from buffer cst
        uint32_t ah[2][4], al[2][4], bh[8], bl[8];
        ldsm4(ah[0], sb + cst + OFF_AHI + aoff[0]);
        ldsm4(ah[1], sb + cst + OFF_AHI + aoff[1]);
        ldsm4(al[0], sb + cst + OFF_ALO + aoff[0]);
        ldsm4(al[1], sb + cst + OFF_ALO + aoff[1]);
        ldsm4(&bh[0], sb + cst + OFF_BHI + boff[0]);
        ldsm4(&bh[4], sb + cst + OFF_BHI + boff[1]);
        #pragma unroll
        for (int s = 0; s < 2; s++)
            #pragma unroll
            for (int j = 0; j < 4; j++) {
                mma_bf16(acc[s][j], ah[s], bh[2*j], bh[2*j + 1]);   // hi*hi
                mma_bf16(acc[s][j], al[s], bh[2*j], bh[2*j + 1]);   // lo*hi
            }
        ldsm4(&bl[0], sb + cst + OFF_BLO + boff[0]);
        ldsm4(&bl[4], sb + cst + OFF_BLO + boff[1]);
        #pragma unroll
        for (int s = 0; s < 2; s++)
            #pragma unroll
            for (int j = 0; j < 4; j++)
                mma_bf16(acc[s][j], ah[s], bl[2*j], bl[2*j + 1]);   // hi*lo

        // stage chunk c+1 into buffer nst (overlaps other warps' MMA)
        if (c + 1 < NCH) {
            #pragma unroll
            for (int i = 0; i < 2; i++) {
                const uint32_t byt = nst + fbytA + (uint32_t)(4*i) * 2u;
                uint32_t h01, l01, h23, l23;
                cvt_hilo(px[i].x, px[i].y, h01, l01);
                cvt_hilo(px[i].z, px[i].w, h23, l23);
                *(uint2*)(smtiles + OFF_AHI + byt) = make_uint2(h01, h23);
                *(uint2*)(smtiles + OFF_ALO + byt) = make_uint2(l01, l23);
                uint32_t wh01, wl01, wh23, wl23;
                cvt_hilo(pw[i].x, pw[i].y, wh01, wl01);
                cvt_hilo(pw[i].z, pw[i].w, wh23, wl23);
                *(uint2*)(smtiles + OFF_BHI + byt) = make_uint2(wh01, wh23);
                *(uint2*)(smtiles + OFF_BLO + byt) = make_uint2(wl01, wl23);
            }
        }
        __syncthreads();
    }

    // ---- acc -> epi[kg][64][68] (k-half partials) ----
    float* epi = (float*)smtiles;
    {
        float* ep = epi + kg * TM * 68;
        const int rl = lane >> 2;
        const int cq = (lane & 3) * 2;
        #pragma unroll
        for (int s = 0; s < 2; s++) {
            const int r0 = mg*32 + s*16 + rl;
            #pragma unroll
            for (int j = 0; j < 4; j++) {
                const int col = ng*32 + j*8 + cq;
                *(float2*)&ep[(r0    )*68 + col] = make_float2(acc[s][j][0], acc[s][j][1]);
                *(float2*)&ep[(r0 + 8)*68 + col] = make_float2(acc[s][j][2], acc[s][j][3]);
            }
        }
    }
    __syncthreads();

    // ---- LN / softmax / top-2 (8 warps x 8 tokens) ----
    const float g0v = gamma[lane], g1v = gamma[lane + 32];
    const float bb0 = beta[lane], bb1 = beta[lane + 32];
    const float invt = 1.0f / (temp[0] + 1e-6f);

    for (int e = lane; e < E_; e += 32) s_exl[wid][e] = 0.0f;

    float zacc = 0.0f;
    for (int t = wid*8; t < wid*8 + 8; t++) {
        const float v0 = epi[t*68 + lane]      + epi[TM*68 + t*68 + lane];
        const float v1 = epi[t*68 + lane + 32] + epi[TM*68 + t*68 + lane + 32];
        float sm = v0 + v1;
        #pragma unroll
        for (int o = 16; o; o >>= 1) sm += __shfl_xor_sync(~0u, sm, o);
        const float mu = sm * (1.0f/64.0f);
        const float d0 = v0 - mu, d1 = v1 - mu;
        float q = d0*d0 + d1*d1;
        #pragma unroll
        for (int o = 16; o; o >>= 1) q += __shfl_xor_sync(~0u, q, o);
        const float inv = rsqrtf(q * (1.0f/64.0f) + 1e-5f);
        const float y0 = d0*inv*g0v + bb0;
        const float y1 = d1*inv*g1v + bb1;
        zacc += y0*y0 + y1*y1;
        const float sc0 = y0*invt, sc1 = y1*invt;
        float m = fmaxf(sc0, sc1);
        #pragma unroll
        for (int o = 16; o; o >>= 1) m = fmaxf(m, __shfl_xor_sync(~0u, m, o));
        const float ex0 = __expf(sc0 - m), ex1 = __expf(sc1 - m);
        float es = ex0 + ex1;
        #pragma unroll
        for (int o = 16; o; o >>= 1) es += __shfl_xor_sync(~0u, es, o);
        const float rinv = 1.0f / es;
        const float p0 = ex0 * rinv, p1 = ex1 * rinv;
        float bv; int bi;
        if (p0 >= p1) { bv = p0; bi = lane; } else { bv = p1; bi = lane + 32; }
        #pragma unroll
        for (int o = 16; o; o >>= 1) {
            float ov = __shfl_xor_sync(~0u, bv, o);
            int   oi = __shfl_xor_sync(~0u, bi, o);
            if (ov > bv || (ov == bv && oi < bi)) { bv = ov; bi = oi; }
        }
        const float w1 = bv; const int i1 = bi;
        const float c0 = (lane      == i1) ? -1.0f : p0;
        const float c1 = (lane + 32 == i1) ? -1.0f : p1;
        if (c0 >= c1) { bv = c0; bi = lane; } else { bv = c1; bi = lane + 32; }
        #pragma unroll
        for (int o = 16; o; o >>= 1) {
            float ov = __shfl_xor_sync(~0u, bv, o);
            int   oi = __shfl_xor_sync(~0u, bi, o);
            if (ov > bv || (ov == bv && oi < bi)) { bv = ov; bi = oi; }
        }
        const float w2 = bv; const int i2 = bi;

        const size_t base = (size_t)(gt0 + t) * E_;
        out_rw[base + lane]      = p0;
        out_rw[base + lane + 32] = p1;
        out_disp[base + lane]      = (lane == i1 || lane == i2)           ? p0 : 0.0f;
        out_disp[base + lane + 32] = (lane + 32 == i1 || lane + 32 == i2) ? p1 : 0.0f;

        if (i1 == lane)           s_exl[wid][lane]      += w1;
        else if (i1 == lane + 32) s_exl[wid][lane + 32] += w1;
        if (i2 == lane)           s_exl[wid][lane]      += w2;
        else if (i2 == lane + 32) s_exl[wid][lane + 32] += w2;
    }
    #pragma unroll
    for (int o = 16; o; o >>= 1) zacc += __shfl_xor_sync(~0u, zacc, o);
    if (lane == 0) s_z[wid] = zacc;
    __syncthreads();

    if (tid < E_) {
        float a = 0.0f;
        #pragma unroll
        for (int w = 0; w < 8; w++) a += s_exl[w][tid];
        g_load_part[blk][tid] = a;
    }
    if (tid == 0)
        g_z_part[blk] = s_z[0]+s_z[1]+s_z[2]+s_z[3]+s_z[4]+s_z[5]+s_z[6]+s_z[7];

    // ---- last-block finalize (deterministic) ----
    __threadfence();
    if (tid == 0) s_last = (atomicAdd(&g_cnt, 1) == NBLK - 1) ? 1u : 0u;
    __syncthreads();
    if (!s_last) return;
    if (tid == 0) g_cnt = 0;
    __threadfence();

    float* red = (float*)smtiles;
    const int b = tid >> 6, e = tid & 63;
    float l = 0.0f;
    #pragma unroll 8
    for (int k = 0; k < NBPB; k++) l += g_load_part[b * NBPB + k][e];
    l *= (1.0f / S_);
    const float zc = g_z_part[tid];

    __syncthreads();
    red[tid] = l; __syncthreads();
    for (int o = 128; o; o >>= 1) { if (tid < o) red[tid] += red[tid + o]; __syncthreads(); }
    const float mean = red[0] * (1.0f / 256.0f);
    __syncthreads();

    const float dd = l - mean;
    red[tid] = dd * dd; __syncthreads();
    for (int o = 128; o; o >>= 1) { if (tid < o) red[tid] += red[tid + o]; __syncthreads(); }
    const float var = red[0] * (1.0f / 255.0f);
    __syncthreads();

    red[tid] = zc; __syncthreads();
    for (int o = 128; o; o >>= 1) { if (tid < o) red[tid] += red[tid + o]; __syncthreads(); }

    if (tid == 0) {
        const float zmean = red[0] / (float)((size_t)N_ * E_);
        const float lb = (sqrtf(var) / mean) * 10.0f;
        out_loss[0] = 0.001f * zmean + 0.1f * lb;
    }
}

extern "C" void kernel_launch(void* const* d_in, const int* in_sizes, int n_in,
                              void* d_out, int out_size)
{
    (void)in_sizes; (void)n_in; (void)out_size;
    const float* x     = (const float*)d_in[0];
    const float* W     = (const float*)d_in[1];
    const float* gamma = (const float*)d_in[2];
    const float* beta  = (const float*)d_in[3];
    const float* temp  = (const float*)d_in[4];

    float* out  = (float*)d_out;
    float* rw   = out;
    float* disp = out + (size_t)N_ * E_;
    float* loss = out + (size_t)2 * N_ * E_;

    router_main<<<NBLK, 256>>>(x, W, gamma, beta, temp, rw, disp, loss);
}

// round 12
// speedup vs baseline: 1.6545x; 1.0852x over previous
#include <cuda_runtime.h>
#include <cuda_bf16.h>
#include <cstdint>
#include <cstddef>

#define B_   4
#define S_   4096
#define D_   2048
#define E_   64
#define N_   (B_*S_)          // 16384
#define TM   128              // tokens per block
#define NBLK (N_/TM)          // 128 blocks
#define KC   32               // k per chunk
#define NCH  (D_/KC)          // 64 chunks
#define NBPB (S_/TM)          // 32 blocks per batch
#define NTHR 512

// dynamic smem: tiles (row stride 40 bf16 = 80B, conflict-free ldmatrix)
#define OFF_AHI 0
#define OFF_ALO (TM*80)            // 10240
#define OFF_BHI (2*TM*80)          // 20480
#define OFF_BLO (2*TM*80 + E_*80)  // 25600
#define TILE_BYTES (2*TM*80 + 2*E_*80)   // 30720
#define EPI_BYTES (2*TM*68*4)            // 69632 (union; epi aliases tiles)
#define SMEM_DYN  EPI_BYTES

__device__ float g_load_part[NBLK][E_];
__device__ float g_z_part[NBLK];
__device__ unsigned int g_cnt = 0;

__device__ __forceinline__ uint32_t smem_u32(const void* p) {
    uint32_t a;
    asm("{ .reg .u64 t; cvta.to.shared.u64 t, %1; cvt.u32.u64 %0, t; }" : "=r"(a) : "l"(p));
    return a;
}
__device__ __forceinline__ void ldsm4(uint32_t* r, uint32_t addr) {
    asm volatile("ldmatrix.sync.aligned.m8n8.x4.shared.b16 {%0,%1,%2,%3}, [%4];"
                 : "=r"(r[0]), "=r"(r[1]), "=r"(r[2]), "=r"(r[3]) : "r"(addr));
}
__device__ __forceinline__ void mma_bf16(float* d, const uint32_t* a, uint32_t b0, uint32_t b1) {
    asm volatile(
        "mma.sync.aligned.m16n8k16.row.col.f32.bf16.bf16.f32 "
        "{%0,%1,%2,%3}, {%4,%5,%6,%7}, {%8,%9}, {%0,%1,%2,%3};"
        : "+f"(d[0]), "+f"(d[1]), "+f"(d[2]), "+f"(d[3])
        : "r"(a[0]), "r"(a[1]), "r"(a[2]), "r"(a[3]), "r"(b0), "r"(b1));
}
__device__ __forceinline__ void cvt_hilo(float a, float b, uint32_t &hi, uint32_t &lo) {
    __nv_bfloat162 h = __floats2bfloat162_rn(a, b);
    hi = *reinterpret_cast<uint32_t*>(&h);
    float ra = a - __bfloat162float(h.x);
    float rb = b - __bfloat162float(h.y);
    __nv_bfloat162 l = __floats2bfloat162_rn(ra, rb);
    lo = *reinterpret_cast<uint32_t*>(&l);
}

__global__ void __launch_bounds__(NTHR) router_main(
    const float* __restrict__ x, const float* __restrict__ W,
    const float* __restrict__ gamma, const float* __restrict__ beta,
    const float* __restrict__ temp,
    float* __restrict__ out_rw, float* __restrict__ out_disp,
    float* __restrict__ out_loss)
{
    extern __shared__ __align__(16) char smtiles[];     // tiles; epi[2][128][68] aliases
    __shared__ float s_exl[16][E_];
    __shared__ float s_z[16];
    __shared__ unsigned int s_last;

    const uint32_t sb = smem_u32(smtiles);
    const int tid = threadIdx.x;
    const int wid = tid >> 5, lane = tid & 31;
    const int blk = blockIdx.x;
    const int gt0 = blk * TM;

    // ---- fill mapping ----
    const int arow = tid >> 2, ak0 = (tid & 3) * 8;     // A: 128 rows, 4 thr/row, 8 floats
    const int brow = tid >> 3, bk0 = (tid & 7) * 4;     // B: 64 rows, 8 thr/row, 4 floats
    const float* xbase = x + (size_t)(gt0 + arow) * D_ + ak0;
    const float* wbase = W + (size_t)brow * D_ + bk0;

    float4 px[2], pw;
    #pragma unroll
    for (int i = 0; i < 2; i++) px[i] = *(const float4*)(xbase + 4*i);
    pw = *(const float4*)(wbase);

    // ---- warp tile: m32 x n32 x k16 (mg:4, ng:2, kg:2) ----
    const int mg = wid & 3, ng = (wid >> 2) & 1, kg = wid >> 3;
    const int g = lane >> 3, rif = lane & 7;
    const uint32_t kgb = (uint32_t)kg * 32u;    // k16 byte offset
    uint32_t aoff[2], boff[2];
    #pragma unroll
    for (int s = 0; s < 2; s++)
        aoff[s] = (uint32_t)(mg*32 + s*16 + (g & 1)*8 + rif) * 80u + (uint32_t)((g >> 1)*8) * 2u + kgb;
    #pragma unroll
    for (int j = 0; j < 2; j++)
        boff[j] = (uint32_t)(ng*32 + j*16 + (g >> 1)*8 + rif) * 80u + (uint32_t)((g & 1)*8) * 2u + kgb;

    float acc[2][4][4];
    #pragma unroll
    for (int s = 0; s < 2; s++)
        #pragma unroll
        for (int j = 0; j < 4; j++)
            #pragma unroll
            for (int i = 0; i < 4; i++) acc[s][j][i] = 0.0f;

    for (int c = 0; c < NCH; c++) {
        // stage regs -> smem (bf16 hi/lo)
        #pragma unroll
        for (int i = 0; i < 2; i++) {
            const uint32_t byt = (uint32_t)arow * 80u + (uint32_t)(ak0 + 4*i) * 2u;
            uint32_t h01, l01, h23, l23;
            cvt_hilo(px[i].x, px[i].y, h01, l01);
            cvt_hilo(px[i].z, px[i].w, h23, l23);
            *(uint2*)(smtiles + OFF_AHI + byt) = make_uint2(h01, h23);
            *(uint2*)(smtiles + OFF_ALO + byt) = make_uint2(l01, l23);
        }
        {
            const uint32_t byt = (uint32_t)brow * 80u + (uint32_t)bk0 * 2u;
            uint32_t wh01, wl01, wh23, wl23;
            cvt_hilo(pw.x, pw.y, wh01, wl01);
            cvt_hilo(pw.z, pw.w, wh23, wl23);
            *(uint2*)(smtiles + OFF_BHI + byt) = make_uint2(wh01, wh23);
            *(uint2*)(smtiles + OFF_BLO + byt) = make_uint2(wl01, wl23);
        }
        __syncthreads();

        if (c + 1 < NCH) {
            const int kb = (c + 1) * KC;
            #pragma unroll
            for (int i = 0; i < 2; i++) px[i] = *(const float4*)(xbase + kb + 4*i);
            pw = *(const float4*)(wbase + kb);
        }

        // one k16 step per warp (its k-half)
        uint32_t ah[2][4], al[2][4], bh[8], bl[8];
        ldsm4(ah[0], sb + OFF_AHI + aoff[0]);
        ldsm4(ah[1], sb + OFF_AHI + aoff[1]);
        ldsm4(al[0], sb + OFF_ALO + aoff[0]);
        ldsm4(al[1], sb + OFF_ALO + aoff[1]);
        ldsm4(&bh[0], sb + OFF_BHI + boff[0]);
        ldsm4(&bh[4], sb + OFF_BHI + boff[1]);
        #pragma unroll
        for (int s = 0; s < 2; s++)
            #pragma unroll
            for (int j = 0; j < 4; j++) {
                mma_bf16(acc[s][j], ah[s], bh[2*j], bh[2*j + 1]);   // hi*hi
                mma_bf16(acc[s][j], al[s], bh[2*j], bh[2*j + 1]);   // lo*hi
            }
        ldsm4(&bl[0], sb + OFF_BLO + boff[0]);
        ldsm4(&bl[4], sb + OFF_BLO + boff[1]);
        #pragma unroll
        for (int s = 0; s < 2; s++)
            #pragma unroll
            for (int j = 0; j < 4; j++)
                mma_bf16(acc[s][j], ah[s], bl[2*j], bl[2*j + 1]);   // hi*lo
        __syncthreads();
    }

    // ---- acc -> epi[kg][128][68] (k-half partials) ----
    float* epi = (float*)smtiles;
    {
        float* ep = epi + kg * TM * 68;
        const int rl = lane >> 2;
        const int cq = (lane & 3) * 2;
        #pragma unroll
        for (int s = 0; s < 2; s++) {
            const int r0 = mg*32 + s*16 + rl;
            #pragma unroll
            for (int j = 0; j < 4; j++) {
                const int col = ng*32 + j*8 + cq;
                *(float2*)&ep[(r0    )*68 + col] = make_float2(acc[s][j][0], acc[s][j][1]);
                *(float2*)&ep[(r0 + 8)*68 + col] = make_float2(acc[s][j][2], acc[s][j][3]);
            }
        }
    }
    __syncthreads();

    // ---- LN / softmax / top-2 (16 warps x 8 tokens) ----
    const float g0v = gamma[lane], g1v = gamma[lane + 32];
    const float bb0 = beta[lane], bb1 = beta[lane + 32];
    const float invt = 1.0f / (temp[0] + 1e-6f);

    for (int e = lane; e < E_; e += 32) s_exl[wid][e] = 0.0f;

    float zacc = 0.0f;
    for (int t = wid*8; t < wid*8 + 8; t++) {
        const float v0 = epi[t*68 + lane]      + epi[TM*68 + t*68 + lane];
        const float v1 = epi[t*68 + lane + 32] + epi[TM*68 + t*68 + lane + 32];
        float sm = v0 + v1;
        #pragma unroll
        for (int o = 16; o; o >>= 1) sm += __shfl_xor_sync(~0u, sm, o);
        const float mu = sm * (1.0f/64.0f);
        const float d0 = v0 - mu, d1 = v1 - mu;
        float q = d0*d0 + d1*d1;
        #pragma unroll
        for (int o = 16; o; o >>= 1) q += __shfl_xor_sync(~0u, q, o);
        const float inv = rsqrtf(q * (1.0f/64.0f) + 1e-5f);
        const float y0 = d0*inv*g0v + bb0;
        const float y1 = d1*inv*g1v + bb1;
        zacc += y0*y0 + y1*y1;
        const float sc0 = y0*invt, sc1 = y1*invt;
        float m = fmaxf(sc0, sc1);
        #pragma unroll
        for (int o = 16; o; o >>= 1) m = fmaxf(m, __shfl_xor_sync(~0u, m, o));
        const float ex0 = __expf(sc0 - m), ex1 = __expf(sc1 - m);
        float es = ex0 + ex1;
        #pragma unroll
        for (int o = 16; o; o >>= 1) es += __shfl_xor_sync(~0u, es, o);
        const float rinv = 1.0f / es;
        const float p0 = ex0 * rinv, p1 = ex1 * rinv;
        float bv; int bi;
        if (p0 >= p1) { bv = p0; bi = lane; } else { bv = p1; bi = lane + 32; }
        #pragma unroll
        for (int o = 16; o; o >>= 1) {
            float ov = __shfl_xor_sync(~0u, bv, o);
            int   oi = __shfl_xor_sync(~0u, bi, o);
            if (ov > bv || (ov == bv && oi < bi)) { bv = ov; bi = oi; }
        }
        const float w1 = bv; const int i1 = bi;
        const float c0 = (lane      == i1) ? -1.0f : p0;
        const float c1 = (lane + 32 == i1) ? -1.0f : p1;
        if (c0 >= c1) { bv = c0; bi = lane; } else { bv = c1; bi = lane + 32; }
        #pragma unroll
        for (int o = 16; o; o >>= 1) {
            float ov = __shfl_xor_sync(~0u, bv, o);
            int   oi = __shfl_xor_sync(~0u, bi, o);
            if (ov > bv || (ov == bv && oi < bi)) { bv = ov; bi = oi; }
        }
        const float w2 = bv; const int i2 = bi;

        const size_t base = (size_t)(gt0 + t) * E_;
        out_rw[base + lane]      = p0;
        out_rw[base + lane + 32] = p1;
        out_disp[base + lane]      = (lane == i1 || lane == i2)           ? p0 : 0.0f;
        out_disp[base + lane + 32] = (lane + 32 == i1 || lane + 32 == i2) ? p1 : 0.0f;

        if (i1 == lane)           s_exl[wid][lane]      += w1;
        else if (i1 == lane + 32) s_exl[wid][lane + 32] += w1;
        if (i2 == lane)           s_exl[wid][lane]      += w2;
        else if (i2 == lane + 32) s_exl[wid][lane + 32] += w2;
    }
    #pragma unroll
    for (int o = 16; o; o >>= 1) zacc += __shfl_xor_sync(~0u, zacc, o);
    if (lane == 0) s_z[wid] = zacc;
    __syncthreads();

    if (tid < E_) {
        float a = 0.0f;
        #pragma unroll
        for (int w = 0; w < 16; w++) a += s_exl[w][tid];
        g_load_part[blk][tid] = a;
    }
    if (tid == 0) {
        float a = 0.0f;
        #pragma unroll
        for (int w = 0; w < 16; w++) a += s_z[w];
        g_z_part[blk] = a;
    }

    // ---- last-block finalize (deterministic) ----
    __threadfence();
    if (tid == 0) s_last = (atomicAdd(&g_cnt, 1) == NBLK - 1) ? 1u : 0u;
    __syncthreads();
    if (!s_last) return;
    if (tid == 0) g_cnt = 0;
    __threadfence();

    float* red = (float*)smtiles;    // 512-float scratch
    const int b = tid >> 6, e = tid & 63;
    float l = 0.0f;
    if (tid < 256) {
        #pragma unroll 8
        for (int k = 0; k < NBPB; k++) l += g_load_part[b * NBPB + k][e];
        l *= (1.0f / S_);
    }
    const float zc = (tid < NBLK) ? g_z_part[tid] : 0.0f;

    __syncthreads();
    red[tid] = l; __syncthreads();
    for (int o = 256; o; o >>= 1) { if (tid < o) red[tid] += red[tid + o]; __syncthreads(); }
    const float mean = red[0] * (1.0f / 256.0f);
    __syncthreads();

    const float dd = (tid < 256) ? (l - mean) : 0.0f;
    red[tid] = dd * dd; __syncthreads();
    for (int o = 256; o; o >>= 1) { if (tid < o) red[tid] += red[tid + o]; __syncthreads(); }
    const float var = red[0] * (1.0f / 255.0f);
    __syncthreads();

    red[tid] = zc; __syncthreads();
    for (int o = 256; o; o >>= 1) { if (tid < o) red[tid] += red[tid + o]; __syncthreads(); }

    if (tid == 0) {
        const float zmean = red[0] / (float)((size_t)N_ * E_);
        const float lb = (sqrtf(var) / mean) * 10.0f;
        out_loss[0] = 0.001f * zmean + 0.1f * lb;
    }
}

extern "C" void kernel_launch(void* const* d_in, const int* in_sizes, int n_in,
                              void* d_out, int out_size)
{
    (void)in_sizes; (void)n_in; (void)out_size;
    const float* x     = (const float*)d_in[0];
    const float* W     = (const float*)d_in[1];
    const float* gamma = (const float*)d_in[2];
    const float* beta  = (const float*)d_in[3];
    const float* temp  = (const float*)d_in[4];

    float* out  = (float*)d_out;
    float* rw   = out;
    float* disp = out + (size_t)N_ * E_;
    float* loss = out + (size_t)2 * N_ * E_;

    cudaFuncSetAttribute(router_main, cudaFuncAttributeMaxDynamicSharedMemorySize, SMEM_DYN);
    router_main<<<NBLK, NTHR, SMEM_DYN>>>(x, W, gamma, beta, temp, rw, disp, loss);
}